// round 12
// baseline (speedup 1.0000x reference)
#include <cuda_runtime.h>
#include <cooperative_groups.h>
#include <cstdint>

namespace cg = cooperative_groups;

// Problem constants
static constexpr int B = 32;
static constexpr int L = 4096;
static constexpr int C = 8;
static constexpr int T = 64;
static constexpr long long NELEM = (long long)B * L * C;   // 1,048,576

static constexpr int GRID_BLOCKS  = 1024;
static constexpr int BLOCK_THREADS = 128;
// 1024*128 threads * 8 elems = 1,048,576 == NELEM exactly (reduce phase)
// 1024*128 threads * 8 l's   = output coverage (lif phase, R10 shape)

// Deterministic scratch (fixed-slot partials)
__device__ double g_psum[GRID_BLOCKS];
__device__ double g_psumsq[GRID_BLOCKS];
__device__ float  g_mean;
__device__ float  g_inv;   // rsqrt.approx(var + eps)

__device__ __forceinline__ float rsqrt_approx(float x) {
    float r;
    asm("rsqrt.approx.f32 %0, %1;" : "=f"(r) : "f"(x));
    return r;
}

// ---------------------------------------------------------------------------
// Fused kernel (cooperative):
// Phase 1: grid-wide delta reduction. Each thread owns 8 contiguous idx
//   [base, base+8); loads window [base-8, base+8) as 4 independent float4s.
//   delta_j = a[j+8] - a[j] (= in[idx] - in[idx-C], C=8, stride along l);
//   head chunk (base % (L*C) == 0) is exactly the 8 l==0 slots -> zero.
//   f32 warp shuffle -> double warp partials -> g_psum[block].
// grid.sync() -> block 0 folds 1024 double partials -> g_mean / g_inv.
// grid.sync() -> Phase 2: R10's proven lif loop byte-for-byte: one thread =
//   8 l's as two disjoint 4-chunks (lA, lA+L/2), two independent 512B-burst
//   float4 .cs stores per t. out[((b*T+t)*C+c)*L + l].
// ---------------------------------------------------------------------------
__global__ void __launch_bounds__(BLOCK_THREADS) fused_kernel(
    const float* __restrict__ in,
    const float* __restrict__ enc_w,
    const float* __restrict__ enc_b,
    const float* __restrict__ bn_gamma,
    const float* __restrict__ bn_beta,
    float* __restrict__ out)
{
    cg::grid_group grid = cg::this_grid();

    __shared__ float sw[T];
    __shared__ float sb[T];
    if (threadIdx.x < T) {
        sw[threadIdx.x] = enc_w[threadIdx.x];   // enc_w is [T,1]
        sb[threadIdx.x] = enc_b[threadIdx.x];
    }

    // ---------------- Phase 1: reduce ----------------
    {
        const int tid  = blockIdx.x * BLOCK_THREADS + threadIdx.x;
        const int base = tid * 8;
        const bool head = (base & (L * C - 1)) == 0;   // l==0 chunk

        float s = 0.0f, q = 0.0f;
        if (!head) {
            const float* p = in + base;
            float4 v0 = *reinterpret_cast<const float4*>(p - 8);
            float4 v1 = *reinterpret_cast<const float4*>(p - 4);
            float4 v2 = *reinterpret_cast<const float4*>(p);
            float4 v3 = *reinterpret_cast<const float4*>(p + 4);
            float a[16] = { v0.x, v0.y, v0.z, v0.w,  v1.x, v1.y, v1.z, v1.w,
                            v2.x, v2.y, v2.z, v2.w,  v3.x, v3.y, v3.z, v3.w };
            #pragma unroll
            for (int j = 0; j < 8; ++j) {
                float delta = a[j + 8] - a[j];
                s += delta;
                q  = fmaf(delta, delta, q);
            }
        }

        #pragma unroll
        for (int o = 16; o > 0; o >>= 1) {
            s += __shfl_down_sync(0xffffffffu, s, o);
            q += __shfl_down_sync(0xffffffffu, q, o);
        }

        __shared__ double ws[4], wq[4];
        const int lane = threadIdx.x & 31;
        const int warp = threadIdx.x >> 5;   // 0..3
        if (lane == 0) { ws[warp] = (double)s; wq[warp] = (double)q; }
        __syncthreads();
        if (threadIdx.x == 0) {
            g_psum[blockIdx.x]   = (ws[0] + ws[1]) + (ws[2] + ws[3]);
            g_psumsq[blockIdx.x] = (wq[0] + wq[1]) + (wq[2] + wq[3]);
        }
    }

    grid.sync();

    // Block 0 folds the 1024 partials
    if (blockIdx.x == 0) {
        const int t = threadIdx.x;
        double ds = 0.0, dq = 0.0;
        #pragma unroll
        for (int k = 0; k < 8; ++k) {
            ds += g_psum[t + k * 128];
            dq += g_psumsq[t + k * 128];
        }
        #pragma unroll
        for (int o = 16; o > 0; o >>= 1) {
            ds += __shfl_down_sync(0xffffffffu, ds, o);
            dq += __shfl_down_sync(0xffffffffu, dq, o);
        }
        __shared__ double fs[4], fq[4];
        const int lane = t & 31;
        const int warp = t >> 5;
        if (lane == 0) { fs[warp] = ds; fq[warp] = dq; }
        __syncthreads();
        if (t == 0) {
            double S = (fs[0] + fs[1]) + (fs[2] + fs[3]);
            double Q = (fq[0] + fq[1]) + (fq[2] + fq[3]);
            double mean = S / (double)NELEM;
            double var  = Q / (double)NELEM - mean * mean;
            g_mean = (float)mean;
            g_inv  = rsqrt_approx((float)var + 1e-5f);
        }
    }

    grid.sync();

    // ---------------- Phase 2: LIF + spike stores (R10 shape) ----------------
    const int idx = blockIdx.x * BLOCK_THREADS + threadIdx.x;  // 0 .. 131071
    const int lv  = idx & ((L / 8) - 1);        // 0..511
    const int c   = (idx >> 9) & (C - 1);
    const int b   = idx >> 12;
    const int lA  = lv * 4;                     // chunk A: [lA, lA+4)
    const int lB  = lA + (L / 2);               // chunk B: [lB, lB+4)

    const float mean = g_mean;
    const float inv  = g_inv;
    const float ga   = bn_gamma[0];
    const float be   = bn_beta[0];

    const float* inp = in + ((long long)b * L) * C + c;

    float dA[4], dB[4];
    #pragma unroll
    for (int j = 0; j < 4; ++j) {
        int la = lA + j;
        float deltaA = (la == 0) ? 0.0f : (inp[la * C] - inp[(la - 1) * C]);
        float xa = (deltaA - mean) * inv;
        dA[j] = xa * ga + be;

        int lb = lB + j;
        float deltaB = inp[lb * C] - inp[(lb - 1) * C];   // lB >= 2048, never 0
        float xb = (deltaB - mean) * inv;
        dB[j] = xb * ga + be;
    }

    float vA0 = 0.f, vA1 = 0.f, vA2 = 0.f, vA3 = 0.f;
    float vB0 = 0.f, vB1 = 0.f, vB2 = 0.f, vB3 = 0.f;

    float* opA = out + (((long long)b * T) * C + c) * L + lA;
    float* opB = opA + (L / 2);

    #pragma unroll 8
    for (int t = 0; t < T; ++t) {
        const float w  = sw[t];
        const float bb = sb[t];
        const long long off = (long long)t * (C * L);
        float4 sa, sbv;

        float x;
        x = fmaf(dA[0], w, bb); vA0 = vA0 + (x - vA0) * 0.5f;
        bool p0 = (vA0 >= 1.0f); sa.x = p0 ? 1.0f : 0.0f; vA0 = p0 ? 0.0f : vA0;
        x = fmaf(dA[1], w, bb); vA1 = vA1 + (x - vA1) * 0.5f;
        bool p1 = (vA1 >= 1.0f); sa.y = p1 ? 1.0f : 0.0f; vA1 = p1 ? 0.0f : vA1;
        x = fmaf(dA[2], w, bb); vA2 = vA2 + (x - vA2) * 0.5f;
        bool p2 = (vA2 >= 1.0f); sa.z = p2 ? 1.0f : 0.0f; vA2 = p2 ? 0.0f : vA2;
        x = fmaf(dA[3], w, bb); vA3 = vA3 + (x - vA3) * 0.5f;
        bool p3 = (vA3 >= 1.0f); sa.w = p3 ? 1.0f : 0.0f; vA3 = p3 ? 0.0f : vA3;

        x = fmaf(dB[0], w, bb); vB0 = vB0 + (x - vB0) * 0.5f;
        bool q0 = (vB0 >= 1.0f); sbv.x = q0 ? 1.0f : 0.0f; vB0 = q0 ? 0.0f : vB0;
        x = fmaf(dB[1], w, bb); vB1 = vB1 + (x - vB1) * 0.5f;
        bool q1 = (vB1 >= 1.0f); sbv.y = q1 ? 1.0f : 0.0f; vB1 = q1 ? 0.0f : vB1;
        x = fmaf(dB[2], w, bb); vB2 = vB2 + (x - vB2) * 0.5f;
        bool q2 = (vB2 >= 1.0f); sbv.z = q2 ? 1.0f : 0.0f; vB2 = q2 ? 0.0f : vB2;
        x = fmaf(dB[3], w, bb); vB3 = vB3 + (x - vB3) * 0.5f;
        bool q3 = (vB3 >= 1.0f); sbv.w = q3 ? 1.0f : 0.0f; vB3 = q3 ? 0.0f : vB3;

        __stcs(reinterpret_cast<float4*>(opA + off), sa);
        __stcs(reinterpret_cast<float4*>(opB + off), sbv);
    }
}

// ---------------------------------------------------------------------------
extern "C" void kernel_launch(void* const* d_in, const int* in_sizes, int n_in,
                              void* d_out, int out_size)
{
    const float* in       = (const float*)d_in[0];
    const float* bn_gamma = (const float*)d_in[1];
    const float* bn_beta  = (const float*)d_in[2];
    const float* enc_w    = (const float*)d_in[3];
    const float* enc_b    = (const float*)d_in[4];
    float* out            = (float*)d_out;

    void* args[] = { (void*)&in, (void*)&enc_w, (void*)&enc_b,
                     (void*)&bn_gamma, (void*)&bn_beta, (void*)&out };
    cudaLaunchCooperativeKernel((void*)fused_kernel,
                                dim3(GRID_BLOCKS), dim3(BLOCK_THREADS),
                                args, 0, (cudaStream_t)0);
}

// round 13
// speedup vs baseline: 1.1392x; 1.1392x over previous
#include <cuda_runtime.h>
#include <cstdint>

// Problem constants
static constexpr int B = 32;
static constexpr int L = 4096;
static constexpr int C = 8;
static constexpr int T = 64;
static constexpr long long NELEM = (long long)B * L * C;   // 1,048,576

static constexpr int RED_BLOCKS  = 256;
static constexpr int RED_THREADS = 256;
// 256*256 threads * 16 elems = 1,048,576 == NELEM exactly

// Deterministic scratch (fixed-slot partials)
__device__ double   g_psum[RED_BLOCKS];
__device__ double   g_psumsq[RED_BLOCKS];
__device__ float    g_mean;
__device__ float    g_inv;    // rsqrt.approx(var + eps)
__device__ unsigned g_count = 0;   // last-block-done counter (reset after use)

__device__ __forceinline__ float rsqrt_approx(float x) {
    float r;
    asm("rsqrt.approx.f32 %0, %1;" : "=f"(r) : "f"(x));
    return r;
}

// ---------------------------------------------------------------------------
// K1: partial sums of delta and delta^2 + fused last-block finalize.
// (R7/R10 proven config.) Triggers the dependent lif launch immediately so
// lif's prelude (launch + raw input loads) overlaps this kernel.
// delta[idx] = in[idx] - in[idx-8] (stride C along l), 0 at l==0.
// ---------------------------------------------------------------------------
__global__ void __launch_bounds__(RED_THREADS) reduce_kernel(const float* __restrict__ in) {
#if __CUDA_ARCH__ >= 900
    cudaTriggerProgrammaticLaunchCompletion();   // let lif start its prelude now
#endif
    const int tid  = blockIdx.x * blockDim.x + threadIdx.x;
    const int base = tid * 16;
    const float* p = in + base;

    float4 v0, v1, v2, v3, v4, v5;
    v2 = *reinterpret_cast<const float4*>(p);
    v3 = *reinterpret_cast<const float4*>(p + 4);
    v4 = *reinterpret_cast<const float4*>(p + 8);
    v5 = *reinterpret_cast<const float4*>(p + 12);
    if (base == 0) {
        v0 = make_float4(0.f, 0.f, 0.f, 0.f);
        v1 = v0;
    } else {
        v0 = *reinterpret_cast<const float4*>(p - 8);
        v1 = *reinterpret_cast<const float4*>(p - 4);
    }

    float a[24] = { v0.x, v0.y, v0.z, v0.w,  v1.x, v1.y, v1.z, v1.w,
                    v2.x, v2.y, v2.z, v2.w,  v3.x, v3.y, v3.z, v3.w,
                    v4.x, v4.y, v4.z, v4.w,  v5.x, v5.y, v5.z, v5.w };

    const bool head = (base & (L * C - 1)) == 0;   // first 16-chunk of a batch row
    float s = 0.0f, q = 0.0f;
    #pragma unroll
    for (int j = 0; j < 16; ++j) {
        float delta = a[j + 8] - a[j];
        if (head && j < 8) delta = 0.0f;
        s += delta;
        q  = fmaf(delta, delta, q);
    }

    #pragma unroll
    for (int o = 16; o > 0; o >>= 1) {
        s += __shfl_down_sync(0xffffffffu, s, o);
        q += __shfl_down_sync(0xffffffffu, q, o);
    }

    __shared__ double ws[8], wq[8];
    const int t    = threadIdx.x;
    const int lane = t & 31;
    const int warp = t >> 5;
    if (lane == 0) { ws[warp] = (double)s; wq[warp] = (double)q; }
    __syncthreads();

    __shared__ bool isLast;
    if (warp == 0) {
        double ds = (lane < 8) ? ws[lane] : 0.0;
        double dq = (lane < 8) ? wq[lane] : 0.0;
        #pragma unroll
        for (int o = 4; o > 0; o >>= 1) {
            ds += __shfl_down_sync(0xffffffffu, ds, o);
            dq += __shfl_down_sync(0xffffffffu, dq, o);
        }
        if (lane == 0) {
            g_psum[blockIdx.x]   = ds;
            g_psumsq[blockIdx.x] = dq;
            __threadfence();
            unsigned prev = atomicAdd(&g_count, 1u);
            isLast = (prev == RED_BLOCKS - 1);
        }
    }
    __syncthreads();

    if (isLast) {
        __threadfence();   // acquire all blocks' partials
        double ds = g_psum[t];
        double dq = g_psumsq[t];
        #pragma unroll
        for (int o = 16; o > 0; o >>= 1) {
            ds += __shfl_down_sync(0xffffffffu, ds, o);
            dq += __shfl_down_sync(0xffffffffu, dq, o);
        }
        __shared__ double fs[8], fq[8];
        if (lane == 0) { fs[warp] = ds; fq[warp] = dq; }
        __syncthreads();
        if (t == 0) {
            double S = 0.0, Q = 0.0;
            #pragma unroll
            for (int w = 0; w < 8; ++w) { S += fs[w]; Q += fq[w]; }
            double mean = S / (double)NELEM;
            double var  = Q / (double)NELEM - mean * mean;
            g_mean  = (float)mean;
            g_inv   = rsqrt_approx((float)var + 1e-5f);
            g_count = 0;   // reset for next graph replay
        }
    }
}

// ---------------------------------------------------------------------------
// K3: main — R10's proven body (45.9us), restructured for PDL:
// prelude (sw/sb, gamma/beta, all 16 raw input loads) runs BEFORE
// cudaGridDependencySynchronize(); only the mean/inv normalize and the
// store loop run after. 1024 CTAs x 128 threads (balanced 6.92 CTAs/SM),
// two independent 512B-burst float4 .cs stores per t.
// out layout: [B, T, C, L] -> ((b*T + t)*C + c)*L + l
// ---------------------------------------------------------------------------
__global__ void __launch_bounds__(128) lif_kernel(
    const float* __restrict__ in,
    const float* __restrict__ enc_w,
    const float* __restrict__ enc_b,
    const float* __restrict__ bn_gamma,
    const float* __restrict__ bn_beta,
    float* __restrict__ out)
{
    __shared__ float sw[T];
    __shared__ float sb[T];
    if (threadIdx.x < T) {
        sw[threadIdx.x] = enc_w[threadIdx.x];   // enc_w is [T,1]
        sb[threadIdx.x] = enc_b[threadIdx.x];
    }

    const int idx = blockIdx.x * blockDim.x + threadIdx.x;  // 0 .. 131071
    const int lv  = idx & ((L / 8) - 1);        // 0..511
    const int c   = (idx >> 9) & (C - 1);
    const int b   = idx >> 12;
    const int lA  = lv * 4;                     // chunk A: [lA, lA+4)
    const int lB  = lA + (L / 2);               // chunk B: [lB, lB+4)

    const float ga = bn_gamma[0];
    const float be = bn_beta[0];

    const float* inp = in + ((long long)b * L) * C + c;

    // Raw deltas — independent of the reduce result, overlap its execution.
    float rA[4], rB[4];
    #pragma unroll
    for (int j = 0; j < 4; ++j) {
        int la = lA + j;
        rA[j] = (la == 0) ? 0.0f : (inp[la * C] - inp[(la - 1) * C]);
        int lb = lB + j;
        rB[j] = inp[lb * C] - inp[(lb - 1) * C];   // lB >= 2048, never 0
    }
    __syncthreads();   // sw/sb visible

#if __CUDA_ARCH__ >= 900
    cudaGridDependencySynchronize();   // wait for reduce grid completion
#endif
    const float mean = g_mean;
    const float inv  = g_inv;

    float dA[4], dB[4];
    #pragma unroll
    for (int j = 0; j < 4; ++j) {
        float xa = (rA[j] - mean) * inv;
        dA[j] = xa * ga + be;
        float xb = (rB[j] - mean) * inv;
        dB[j] = xb * ga + be;
    }

    float vA0 = 0.f, vA1 = 0.f, vA2 = 0.f, vA3 = 0.f;
    float vB0 = 0.f, vB1 = 0.f, vB2 = 0.f, vB3 = 0.f;

    float* opA = out + (((long long)b * T) * C + c) * L + lA;
    float* opB = opA + (L / 2);

    #pragma unroll 8
    for (int t = 0; t < T; ++t) {
        const float w  = sw[t];
        const float bb = sb[t];
        const long long off = (long long)t * (C * L);
        float4 sa, sbv;

        float x;
        x = fmaf(dA[0], w, bb); vA0 = vA0 + (x - vA0) * 0.5f;
        bool p0 = (vA0 >= 1.0f); sa.x = p0 ? 1.0f : 0.0f; vA0 = p0 ? 0.0f : vA0;
        x = fmaf(dA[1], w, bb); vA1 = vA1 + (x - vA1) * 0.5f;
        bool p1 = (vA1 >= 1.0f); sa.y = p1 ? 1.0f : 0.0f; vA1 = p1 ? 0.0f : vA1;
        x = fmaf(dA[2], w, bb); vA2 = vA2 + (x - vA2) * 0.5f;
        bool p2 = (vA2 >= 1.0f); sa.z = p2 ? 1.0f : 0.0f; vA2 = p2 ? 0.0f : vA2;
        x = fmaf(dA[3], w, bb); vA3 = vA3 + (x - vA3) * 0.5f;
        bool p3 = (vA3 >= 1.0f); sa.w = p3 ? 1.0f : 0.0f; vA3 = p3 ? 0.0f : vA3;

        x = fmaf(dB[0], w, bb); vB0 = vB0 + (x - vB0) * 0.5f;
        bool q0 = (vB0 >= 1.0f); sbv.x = q0 ? 1.0f : 0.0f; vB0 = q0 ? 0.0f : vB0;
        x = fmaf(dB[1], w, bb); vB1 = vB1 + (x - vB1) * 0.5f;
        bool q1 = (vB1 >= 1.0f); sbv.y = q1 ? 1.0f : 0.0f; vB1 = q1 ? 0.0f : vB1;
        x = fmaf(dB[2], w, bb); vB2 = vB2 + (x - vB2) * 0.5f;
        bool q2 = (vB2 >= 1.0f); sbv.z = q2 ? 1.0f : 0.0f; vB2 = q2 ? 0.0f : vB2;
        x = fmaf(dB[3], w, bb); vB3 = vB3 + (x - vB3) * 0.5f;
        bool q3 = (vB3 >= 1.0f); sbv.w = q3 ? 1.0f : 0.0f; vB3 = q3 ? 0.0f : vB3;

        __stcs(reinterpret_cast<float4*>(opA + off), sa);
        __stcs(reinterpret_cast<float4*>(opB + off), sbv);
    }
}

// ---------------------------------------------------------------------------
extern "C" void kernel_launch(void* const* d_in, const int* in_sizes, int n_in,
                              void* d_out, int out_size)
{
    const float* in       = (const float*)d_in[0];
    const float* bn_gamma = (const float*)d_in[1];
    const float* bn_beta  = (const float*)d_in[2];
    const float* enc_w    = (const float*)d_in[3];
    const float* enc_b    = (const float*)d_in[4];
    float* out            = (float*)d_out;

    reduce_kernel<<<RED_BLOCKS, RED_THREADS>>>(in);

    // Dependent launch: lif may start its prelude while reduce runs; the
    // device-side cudaGridDependencySynchronize() enforces the data hazard.
    cudaLaunchConfig_t cfg = {};
    cfg.gridDim  = dim3(1024);
    cfg.blockDim = dim3(128);
    cfg.dynamicSmemBytes = 0;
    cfg.stream   = (cudaStream_t)0;
    cudaLaunchAttribute attrs[1];
    attrs[0].id = cudaLaunchAttributeProgrammaticStreamSerialization;
    attrs[0].val.programmaticStreamSerializationAllowed = 1;
    cfg.attrs    = attrs;
    cfg.numAttrs = 1;
    cudaLaunchKernelEx(&cfg, lif_kernel, in, enc_w, enc_b, bn_gamma, bn_beta, out);
}

// round 14
// speedup vs baseline: 1.2351x; 1.0842x over previous
#include <cuda_runtime.h>
#include <cstdint>

// Problem constants
static constexpr int B = 32;
static constexpr int L = 4096;
static constexpr int C = 8;
static constexpr int T = 64;
static constexpr long long NELEM = (long long)B * L * C;   // 1,048,576

static constexpr int RED_BLOCKS  = 512;
static constexpr int RED_THREADS = 128;
// 512*128 threads * 16 elems = 1,048,576 == NELEM exactly

// Deterministic scratch (fixed-slot partials)
__device__ double   g_psum[RED_BLOCKS];
__device__ double   g_psumsq[RED_BLOCKS];
__device__ float    g_mean;
__device__ float    g_inv;    // rsqrt.approx(var + eps)
__device__ unsigned g_count = 0;   // last-block-done counter (reset after use)

__device__ __forceinline__ float rsqrt_approx(float x) {
    float r;
    asm("rsqrt.approx.f32 %0, %1;" : "=f"(r) : "f"(x));
    return r;
}

// ---------------------------------------------------------------------------
// K1: partial sums of delta and delta^2 + fused last-block finalize.
// Proven 16-elem/thread body (6 independent LDG.128), at 512 CTAs x 128
// threads (3.46 CTAs/SM balance — best measured reduce+gap in R11).
// delta[idx] = in[idx] - in[idx-8] (stride C along l), 0 at l==0 (head
// chunk of each batch row zeroes its first 8 slots).
// f32 warp shuffle -> double warp partials -> double block partial; last
// finished block folds 512 doubles -> g_mean / g_inv (counter reset for
// graph replay determinism).
// ---------------------------------------------------------------------------
__global__ void __launch_bounds__(RED_THREADS) reduce_kernel(const float* __restrict__ in) {
    const int tid  = blockIdx.x * blockDim.x + threadIdx.x;
    const int base = tid * 16;
    const float* p = in + base;

    float4 v0, v1, v2, v3, v4, v5;
    v2 = *reinterpret_cast<const float4*>(p);
    v3 = *reinterpret_cast<const float4*>(p + 4);
    v4 = *reinterpret_cast<const float4*>(p + 8);
    v5 = *reinterpret_cast<const float4*>(p + 12);
    if (base == 0) {
        v0 = make_float4(0.f, 0.f, 0.f, 0.f);
        v1 = v0;
    } else {
        v0 = *reinterpret_cast<const float4*>(p - 8);
        v1 = *reinterpret_cast<const float4*>(p - 4);
    }

    float a[24] = { v0.x, v0.y, v0.z, v0.w,  v1.x, v1.y, v1.z, v1.w,
                    v2.x, v2.y, v2.z, v2.w,  v3.x, v3.y, v3.z, v3.w,
                    v4.x, v4.y, v4.z, v4.w,  v5.x, v5.y, v5.z, v5.w };

    const bool head = (base & (L * C - 1)) == 0;   // first 16-chunk of a batch row
    float s = 0.0f, q = 0.0f;
    #pragma unroll
    for (int j = 0; j < 16; ++j) {
        float delta = a[j + 8] - a[j];
        if (head && j < 8) delta = 0.0f;
        s += delta;
        q  = fmaf(delta, delta, q);
    }

    #pragma unroll
    for (int o = 16; o > 0; o >>= 1) {
        s += __shfl_down_sync(0xffffffffu, s, o);
        q += __shfl_down_sync(0xffffffffu, q, o);
    }

    __shared__ double ws[4], wq[4];
    const int t    = threadIdx.x;
    const int lane = t & 31;
    const int warp = t >> 5;     // 0..3
    if (lane == 0) { ws[warp] = (double)s; wq[warp] = (double)q; }
    __syncthreads();

    __shared__ bool isLast;
    if (warp == 0) {
        double ds = (lane < 4) ? ws[lane] : 0.0;
        double dq = (lane < 4) ? wq[lane] : 0.0;
        #pragma unroll
        for (int o = 2; o > 0; o >>= 1) {
            ds += __shfl_down_sync(0xffffffffu, ds, o);
            dq += __shfl_down_sync(0xffffffffu, dq, o);
        }
        if (lane == 0) {
            g_psum[blockIdx.x]   = ds;
            g_psumsq[blockIdx.x] = dq;
            __threadfence();
            unsigned prev = atomicAdd(&g_count, 1u);
            isLast = (prev == RED_BLOCKS - 1);
        }
    }
    __syncthreads();

    if (isLast) {
        __threadfence();   // acquire all blocks' partials
        double ds = g_psum[t]       + g_psum[t + 128]
                  + g_psum[t + 256] + g_psum[t + 384];
        double dq = g_psumsq[t]       + g_psumsq[t + 128]
                  + g_psumsq[t + 256] + g_psumsq[t + 384];
        #pragma unroll
        for (int o = 16; o > 0; o >>= 1) {
            ds += __shfl_down_sync(0xffffffffu, ds, o);
            dq += __shfl_down_sync(0xffffffffu, dq, o);
        }
        __shared__ double fs[4], fq[4];
        if (lane == 0) { fs[warp] = ds; fq[warp] = dq; }
        __syncthreads();
        if (t == 0) {
            double S = (fs[0] + fs[1]) + (fs[2] + fs[3]);
            double Q = (fq[0] + fq[1]) + (fq[2] + fq[3]);
            double mean = S / (double)NELEM;
            double var  = Q / (double)NELEM - mean * mean;
            g_mean  = (float)mean;
            g_inv   = rsqrt_approx((float)var + 1e-5f);
            g_count = 0;   // reset for next graph replay
        }
    }
}

// ---------------------------------------------------------------------------
// K3: main — R10's proven config VERBATIM (45.9us, best measured).
// One thread = 8 l's for one (b, c) as two disjoint 4-chunks (lA, lA+L/2):
// two independent 512B-burst float4 .cs stores per t. 1024 CTAs x 128
// threads (balanced 6.92 CTAs/SM). Plain stream launch (fusion/PDL variants
// all measured slower: R3 +24us, R12 +12us, R13 +4us).
// out layout: [B, T, C, L] -> ((b*T + t)*C + c)*L + l
// ---------------------------------------------------------------------------
__global__ void __launch_bounds__(128) lif_kernel(
    const float* __restrict__ in,
    const float* __restrict__ enc_w,
    const float* __restrict__ enc_b,
    const float* __restrict__ bn_gamma,
    const float* __restrict__ bn_beta,
    float* __restrict__ out)
{
    __shared__ float sw[T];
    __shared__ float sb[T];
    if (threadIdx.x < T) {
        sw[threadIdx.x] = enc_w[threadIdx.x];   // enc_w is [T,1]
        sb[threadIdx.x] = enc_b[threadIdx.x];
    }
    __syncthreads();

    const int idx = blockIdx.x * blockDim.x + threadIdx.x;  // 0 .. 131071
    const int lv  = idx & ((L / 8) - 1);        // 0..511
    const int c   = (idx >> 9) & (C - 1);
    const int b   = idx >> 12;
    const int lA  = lv * 4;                     // chunk A: [lA, lA+4)
    const int lB  = lA + (L / 2);               // chunk B: [lB, lB+4)

    const float mean = g_mean;
    const float inv  = g_inv;
    const float ga   = bn_gamma[0];
    const float be   = bn_beta[0];

    const float* inp = in + ((long long)b * L) * C + c;

    float dA[4], dB[4];
    #pragma unroll
    for (int j = 0; j < 4; ++j) {
        int la = lA + j;
        float deltaA = (la == 0) ? 0.0f : (inp[la * C] - inp[(la - 1) * C]);
        float xa = (deltaA - mean) * inv;
        dA[j] = xa * ga + be;

        int lb = lB + j;
        float deltaB = inp[lb * C] - inp[(lb - 1) * C];   // lB >= 2048, never 0
        float xb = (deltaB - mean) * inv;
        dB[j] = xb * ga + be;
    }

    float vA0 = 0.f, vA1 = 0.f, vA2 = 0.f, vA3 = 0.f;
    float vB0 = 0.f, vB1 = 0.f, vB2 = 0.f, vB3 = 0.f;

    float* opA = out + (((long long)b * T) * C + c) * L + lA;
    float* opB = opA + (L / 2);

    #pragma unroll 8
    for (int t = 0; t < T; ++t) {
        const float w  = sw[t];
        const float bb = sb[t];
        const long long off = (long long)t * (C * L);
        float4 sa, sbv;

        float x;
        x = fmaf(dA[0], w, bb); vA0 = vA0 + (x - vA0) * 0.5f;
        bool p0 = (vA0 >= 1.0f); sa.x = p0 ? 1.0f : 0.0f; vA0 = p0 ? 0.0f : vA0;
        x = fmaf(dA[1], w, bb); vA1 = vA1 + (x - vA1) * 0.5f;
        bool p1 = (vA1 >= 1.0f); sa.y = p1 ? 1.0f : 0.0f; vA1 = p1 ? 0.0f : vA1;
        x = fmaf(dA[2], w, bb); vA2 = vA2 + (x - vA2) * 0.5f;
        bool p2 = (vA2 >= 1.0f); sa.z = p2 ? 1.0f : 0.0f; vA2 = p2 ? 0.0f : vA2;
        x = fmaf(dA[3], w, bb); vA3 = vA3 + (x - vA3) * 0.5f;
        bool p3 = (vA3 >= 1.0f); sa.w = p3 ? 1.0f : 0.0f; vA3 = p3 ? 0.0f : vA3;

        x = fmaf(dB[0], w, bb); vB0 = vB0 + (x - vB0) * 0.5f;
        bool q0 = (vB0 >= 1.0f); sbv.x = q0 ? 1.0f : 0.0f; vB0 = q0 ? 0.0f : vB0;
        x = fmaf(dB[1], w, bb); vB1 = vB1 + (x - vB1) * 0.5f;
        bool q1 = (vB1 >= 1.0f); sbv.y = q1 ? 1.0f : 0.0f; vB1 = q1 ? 0.0f : vB1;
        x = fmaf(dB[2], w, bb); vB2 = vB2 + (x - vB2) * 0.5f;
        bool q2 = (vB2 >= 1.0f); sbv.z = q2 ? 1.0f : 0.0f; vB2 = q2 ? 0.0f : vB2;
        x = fmaf(dB[3], w, bb); vB3 = vB3 + (x - vB3) * 0.5f;
        bool q3 = (vB3 >= 1.0f); sbv.w = q3 ? 1.0f : 0.0f; vB3 = q3 ? 0.0f : vB3;

        __stcs(reinterpret_cast<float4*>(opA + off), sa);
        __stcs(reinterpret_cast<float4*>(opB + off), sbv);
    }
}

// ---------------------------------------------------------------------------
extern "C" void kernel_launch(void* const* d_in, const int* in_sizes, int n_in,
                              void* d_out, int out_size)
{
    const float* in       = (const float*)d_in[0];
    const float* bn_gamma = (const float*)d_in[1];
    const float* bn_beta  = (const float*)d_in[2];
    const float* enc_w    = (const float*)d_in[3];
    const float* enc_b    = (const float*)d_in[4];
    float* out            = (float*)d_out;

    reduce_kernel<<<RED_BLOCKS, RED_THREADS>>>(in);

    const int total_thr = B * C * (L / 8);      // 131072
    lif_kernel<<<total_thr / 128, 128>>>(in, enc_w, enc_b, bn_gamma, bn_beta, out);
}

// round 15
// speedup vs baseline: 1.3039x; 1.0558x over previous
#include <cuda_runtime.h>
#include <cstdint>

// Problem constants
static constexpr int B = 32;
static constexpr int L = 4096;
static constexpr int C = 8;
static constexpr int T = 64;
static constexpr long long NELEM = (long long)B * L * C;   // 1,048,576

static constexpr int RED_BLOCKS  = 1024;
static constexpr int RED_THREADS = 128;
// 1024*128 threads * 8 elems = 1,048,576 == NELEM exactly

// Deterministic scratch
__device__ double   g_psum[RED_BLOCKS];
__device__ double   g_psumsq[RED_BLOCKS];
__device__ float    g_mean;
__device__ float    g_inv;    // rsqrt.approx(var + eps)
__device__ unsigned g_count = 0;   // last-block-done counter (reset after use)
// Transposed deltas: delta_t[b][c][l] = in[b,l,c] - in[b,l-1,c] (0 at l==0).
// 4 MiB, L2-resident; written coalesced by reduce, read coalesced by lif.
__device__ float    g_delta[NELEM];

__device__ __forceinline__ float rsqrt_approx(float x) {
    float r;
    asm("rsqrt.approx.f32 %0, %1;" : "=f"(r) : "f"(x));
    return r;
}

// ---------------------------------------------------------------------------
// K1: delta reduction + TRANSPOSED delta store + fused last-block finalize.
// Layout: idx = ((b*L)+l)*C + c, C=8. Each thread owns 8 contiguous idx
// [base, base+8) == exactly one (b,l) pair's 8 c-values. Loads window
// [base-8, base+8) as 4 independent float4s; d[j] = a[j+8] - a[j]
// (= in[idx] - in[idx-C], stride C along l). Head thread of a batch row
// (base % (L*C) == 0) is precisely l==0 -> all 8 deltas zero.
// Transposed store: d[j] -> g_delta[(b*C + j)*L + l]; for fixed j,
// consecutive threads hit consecutive l -> 128B/warp coalesced STG.32.
// Sum reduction: f32 warp shuffle -> double warp partials -> block partial;
// last finished block folds 1024 doubles -> g_mean/g_inv (counter reset).
// ---------------------------------------------------------------------------
__global__ void __launch_bounds__(RED_THREADS) reduce_kernel(const float* __restrict__ in) {
    const int tid  = blockIdx.x * blockDim.x + threadIdx.x;   // == (b*L + l)
    const int base = tid * 8;
    const bool head = (base & (L * C - 1)) == 0;              // l == 0

    float d[8];
    if (!head) {
        const float* p = in + base;
        float4 v0 = *reinterpret_cast<const float4*>(p - 8);
        float4 v1 = *reinterpret_cast<const float4*>(p - 4);
        float4 v2 = *reinterpret_cast<const float4*>(p);
        float4 v3 = *reinterpret_cast<const float4*>(p + 4);
        d[0] = v2.x - v0.x;  d[1] = v2.y - v0.y;
        d[2] = v2.z - v0.z;  d[3] = v2.w - v0.w;
        d[4] = v3.x - v1.x;  d[5] = v3.y - v1.y;
        d[6] = v3.z - v1.z;  d[7] = v3.w - v1.w;
    } else {
        #pragma unroll
        for (int j = 0; j < 8; ++j) d[j] = 0.0f;
    }

    // Transposed store: (b, l) = tid; dst row j at (b*C + j)*L + l
    {
        const int b = tid >> 12;            // / L
        const int l = tid & (L - 1);
        float* dst = g_delta + ((long long)b * C) * L + l;
        #pragma unroll
        for (int j = 0; j < 8; ++j)
            dst[j * L] = d[j];
    }

    float s = 0.0f, q = 0.0f;
    #pragma unroll
    for (int j = 0; j < 8; ++j) {
        s += d[j];
        q  = fmaf(d[j], d[j], q);
    }

    #pragma unroll
    for (int o = 16; o > 0; o >>= 1) {
        s += __shfl_down_sync(0xffffffffu, s, o);
        q += __shfl_down_sync(0xffffffffu, q, o);
    }

    __shared__ double ws[4], wq[4];
    const int t    = threadIdx.x;
    const int lane = t & 31;
    const int warp = t >> 5;     // 0..3
    if (lane == 0) { ws[warp] = (double)s; wq[warp] = (double)q; }
    __syncthreads();

    __shared__ bool isLast;
    if (warp == 0) {
        double ds = (lane < 4) ? ws[lane] : 0.0;
        double dq = (lane < 4) ? wq[lane] : 0.0;
        #pragma unroll
        for (int o = 2; o > 0; o >>= 1) {
            ds += __shfl_down_sync(0xffffffffu, ds, o);
            dq += __shfl_down_sync(0xffffffffu, dq, o);
        }
        if (lane == 0) {
            g_psum[blockIdx.x]   = ds;
            g_psumsq[blockIdx.x] = dq;
            __threadfence();
            unsigned prev = atomicAdd(&g_count, 1u);
            isLast = (prev == RED_BLOCKS - 1);
        }
    }
    __syncthreads();

    if (isLast) {
        __threadfence();   // acquire all blocks' partials
        double ds = 0.0, dq = 0.0;
        #pragma unroll
        for (int k = 0; k < 8; ++k) {
            ds += g_psum[t + k * 128];
            dq += g_psumsq[t + k * 128];
        }
        #pragma unroll
        for (int o = 16; o > 0; o >>= 1) {
            ds += __shfl_down_sync(0xffffffffu, ds, o);
            dq += __shfl_down_sync(0xffffffffu, dq, o);
        }
        __shared__ double fs[4], fq[4];
        if (lane == 0) { fs[warp] = ds; fq[warp] = dq; }
        __syncthreads();
        if (t == 0) {
            double S = (fs[0] + fs[1]) + (fs[2] + fs[3]);
            double Q = (fq[0] + fq[1]) + (fq[2] + fq[3]);
            double mean = S / (double)NELEM;
            double var  = Q / (double)NELEM - mean * mean;
            g_mean  = (float)mean;
            g_inv   = rsqrt_approx((float)var + 1e-5f);
            g_count = 0;   // reset for next graph replay
        }
    }
}

// ---------------------------------------------------------------------------
// K3: main — R10's proven loop (45.9us) with input loads replaced by TWO
// coalesced float4 loads from the transposed delta buffer (512B/warp,
// L2-resident) instead of 16 strided scalar LDGs (which burned as many L1
// wavefronts as all the stores). Everything else byte-identical: one thread
// = 8 l's as two disjoint 4-chunks (lA, lA+L/2), two independent 512B-burst
// float4 .cs stores per t, 1024 CTAs x 128 threads (balanced 6.92 CTAs/SM).
// out layout: [B, T, C, L] -> ((b*T + t)*C + c)*L + l
// ---------------------------------------------------------------------------
__global__ void __launch_bounds__(128) lif_kernel(
    const float* __restrict__ enc_w,
    const float* __restrict__ enc_b,
    const float* __restrict__ bn_gamma,
    const float* __restrict__ bn_beta,
    float* __restrict__ out)
{
    __shared__ float sw[T];
    __shared__ float sb[T];
    if (threadIdx.x < T) {
        sw[threadIdx.x] = enc_w[threadIdx.x];   // enc_w is [T,1]
        sb[threadIdx.x] = enc_b[threadIdx.x];
    }
    __syncthreads();

    const int idx = blockIdx.x * blockDim.x + threadIdx.x;  // 0 .. 131071
    const int lv  = idx & ((L / 8) - 1);        // 0..511
    const int c   = (idx >> 9) & (C - 1);
    const int b   = idx >> 12;
    const int lA  = lv * 4;                     // chunk A: [lA, lA+4)

    const float mean = g_mean;
    const float inv  = g_inv;
    const float ga   = bn_gamma[0];
    const float be   = bn_beta[0];

    // Coalesced transposed-delta loads (delta_t[b][c][l], 0 already at l==0)
    const float* drow = g_delta + ((long long)b * C + c) * L;
    float4 rA = *reinterpret_cast<const float4*>(drow + lA);
    float4 rB = *reinterpret_cast<const float4*>(drow + lA + (L / 2));

    float dA[4], dB[4];
    {
        const float* pa = &rA.x;
        const float* pb = &rB.x;
        #pragma unroll
        for (int j = 0; j < 4; ++j) {
            float xa = (pa[j] - mean) * inv;
            dA[j] = xa * ga + be;
            float xb = (pb[j] - mean) * inv;
            dB[j] = xb * ga + be;
        }
    }

    float vA0 = 0.f, vA1 = 0.f, vA2 = 0.f, vA3 = 0.f;
    float vB0 = 0.f, vB1 = 0.f, vB2 = 0.f, vB3 = 0.f;

    float* opA = out + (((long long)b * T) * C + c) * L + lA;
    float* opB = opA + (L / 2);

    #pragma unroll 8
    for (int t = 0; t < T; ++t) {
        const float w  = sw[t];
        const float bb = sb[t];
        const long long off = (long long)t * (C * L);
        float4 sa, sbv;

        float x;
        x = fmaf(dA[0], w, bb); vA0 = vA0 + (x - vA0) * 0.5f;
        bool p0 = (vA0 >= 1.0f); sa.x = p0 ? 1.0f : 0.0f; vA0 = p0 ? 0.0f : vA0;
        x = fmaf(dA[1], w, bb); vA1 = vA1 + (x - vA1) * 0.5f;
        bool p1 = (vA1 >= 1.0f); sa.y = p1 ? 1.0f : 0.0f; vA1 = p1 ? 0.0f : vA1;
        x = fmaf(dA[2], w, bb); vA2 = vA2 + (x - vA2) * 0.5f;
        bool p2 = (vA2 >= 1.0f); sa.z = p2 ? 1.0f : 0.0f; vA2 = p2 ? 0.0f : vA2;
        x = fmaf(dA[3], w, bb); vA3 = vA3 + (x - vA3) * 0.5f;
        bool p3 = (vA3 >= 1.0f); sa.w = p3 ? 1.0f : 0.0f; vA3 = p3 ? 0.0f : vA3;

        x = fmaf(dB[0], w, bb); vB0 = vB0 + (x - vB0) * 0.5f;
        bool q0 = (vB0 >= 1.0f); sbv.x = q0 ? 1.0f : 0.0f; vB0 = q0 ? 0.0f : vB0;
        x = fmaf(dB[1], w, bb); vB1 = vB1 + (x - vB1) * 0.5f;
        bool q1 = (vB1 >= 1.0f); sbv.y = q1 ? 1.0f : 0.0f; vB1 = q1 ? 0.0f : vB1;
        x = fmaf(dB[2], w, bb); vB2 = vB2 + (x - vB2) * 0.5f;
        bool q2 = (vB2 >= 1.0f); sbv.z = q2 ? 1.0f : 0.0f; vB2 = q2 ? 0.0f : vB2;
        x = fmaf(dB[3], w, bb); vB3 = vB3 + (x - vB3) * 0.5f;
        bool q3 = (vB3 >= 1.0f); sbv.w = q3 ? 1.0f : 0.0f; vB3 = q3 ? 0.0f : vB3;

        __stcs(reinterpret_cast<float4*>(opA + off), sa);
        __stcs(reinterpret_cast<float4*>(opB + off), sbv);
    }
}

// ---------------------------------------------------------------------------
extern "C" void kernel_launch(void* const* d_in, const int* in_sizes, int n_in,
                              void* d_out, int out_size)
{
    const float* in       = (const float*)d_in[0];
    const float* bn_gamma = (const float*)d_in[1];
    const float* bn_beta  = (const float*)d_in[2];
    const float* enc_w    = (const float*)d_in[3];
    const float* enc_b    = (const float*)d_in[4];
    float* out            = (float*)d_out;

    reduce_kernel<<<RED_BLOCKS, RED_THREADS>>>(in);

    const int total_thr = B * C * (L / 8);      // 131072
    lif_kernel<<<total_thr / 128, 128>>>(enc_w, enc_b, bn_gamma, bn_beta, out);
}

// round 16
// speedup vs baseline: 1.3168x; 1.0099x over previous
#include <cuda_runtime.h>
#include <cstdint>

// Problem constants
static constexpr int B = 32;
static constexpr int L = 4096;
static constexpr int C = 8;
static constexpr int T = 64;
static constexpr long long NELEM = (long long)B * L * C;   // 1,048,576

static constexpr int RED_BLOCKS  = 512;
static constexpr int RED_THREADS = 128;
// 512*128 threads * 16 elems = 1,048,576 == NELEM exactly

// Deterministic scratch
__device__ double   g_psum[RED_BLOCKS];
__device__ double   g_psumsq[RED_BLOCKS];
__device__ float    g_mean;
__device__ float    g_inv;    // rsqrt.approx(var + eps)
__device__ unsigned g_count = 0;   // last-block-done counter (reset after use)
// Transposed deltas: delta_t[b][c][l] = in[b,l,c] - in[b,l-1,c] (0 at l==0).
// 4 MiB, L2-resident; written coalesced by reduce, read coalesced by lif.
__device__ float    g_delta[NELEM];

__device__ __forceinline__ float rsqrt_approx(float x) {
    float r;
    asm("rsqrt.approx.f32 %0, %1;" : "=f"(r) : "f"(x));
    return r;
}

// ---------------------------------------------------------------------------
// K1: delta reduction + TRANSPOSED delta store + fused last-block finalize.
// Layout: idx = ((b*L)+l)*C + c, C=8. Each thread owns 16 contiguous idx
// [base, base+16) == TWO adjacent (b,l) pairs (l0 = even). Loads window
// [base-8, base+16) as 6 independent float4s (R4's proven 5.76us shape).
// d[j] = a[j+8] - a[j] (= in[idx] - in[idx-C], stride C along l); head
// thread of a batch row (base % (L*C) == 0) zeroes j<8 (the l==0 slots).
// Transposed store: float2 {d[j], d[j+8]} -> g_delta[(b*C+j)*L + l0], i.e.
// 8 STG.64; consecutive threads hit consecutive float2 -> 256B/warp.
// Sum: f32 warp shuffle -> double warp partials -> block partial; last
// finished block folds 512 doubles -> g_mean/g_inv (counter reset).
// ---------------------------------------------------------------------------
__global__ void __launch_bounds__(RED_THREADS) reduce_kernel(const float* __restrict__ in) {
    const int tid  = blockIdx.x * blockDim.x + threadIdx.x;   // 0 .. 65535
    const int base = tid * 16;
    const float* p = in + base;

    float4 v0, v1, v2, v3, v4, v5;
    v2 = *reinterpret_cast<const float4*>(p);
    v3 = *reinterpret_cast<const float4*>(p + 4);
    v4 = *reinterpret_cast<const float4*>(p + 8);
    v5 = *reinterpret_cast<const float4*>(p + 12);
    if (base == 0) {
        v0 = make_float4(0.f, 0.f, 0.f, 0.f);
        v1 = v0;
    } else {
        v0 = *reinterpret_cast<const float4*>(p - 8);
        v1 = *reinterpret_cast<const float4*>(p - 4);
    }

    float a[24] = { v0.x, v0.y, v0.z, v0.w,  v1.x, v1.y, v1.z, v1.w,
                    v2.x, v2.y, v2.z, v2.w,  v3.x, v3.y, v3.z, v3.w,
                    v4.x, v4.y, v4.z, v4.w,  v5.x, v5.y, v5.z, v5.w };

    const bool head = (base & (L * C - 1)) == 0;   // first 16-chunk of a batch row
    float d[16];
    #pragma unroll
    for (int j = 0; j < 16; ++j) {
        float delta = a[j + 8] - a[j];
        if (head && j < 8) delta = 0.0f;
        d[j] = delta;
    }

    // Transposed packed store: bl pair index = tid*2 -> (b, l0)
    {
        const int bl = tid * 2;
        const int b  = bl >> 12;            // / L
        const int l0 = bl & (L - 1);        // even
        float* dst = g_delta + ((long long)b * C) * L + l0;
        #pragma unroll
        for (int j = 0; j < 8; ++j) {
            float2 pr = make_float2(d[j], d[j + 8]);
            *reinterpret_cast<float2*>(dst + j * L) = pr;
        }
    }

    float s = 0.0f, q = 0.0f;
    #pragma unroll
    for (int j = 0; j < 16; ++j) {
        s += d[j];
        q  = fmaf(d[j], d[j], q);
    }

    #pragma unroll
    for (int o = 16; o > 0; o >>= 1) {
        s += __shfl_down_sync(0xffffffffu, s, o);
        q += __shfl_down_sync(0xffffffffu, q, o);
    }

    __shared__ double ws[4], wq[4];
    const int t    = threadIdx.x;
    const int lane = t & 31;
    const int warp = t >> 5;     // 0..3
    if (lane == 0) { ws[warp] = (double)s; wq[warp] = (double)q; }
    __syncthreads();

    __shared__ bool isLast;
    if (warp == 0) {
        double ds = (lane < 4) ? ws[lane] : 0.0;
        double dq = (lane < 4) ? wq[lane] : 0.0;
        #pragma unroll
        for (int o = 2; o > 0; o >>= 1) {
            ds += __shfl_down_sync(0xffffffffu, ds, o);
            dq += __shfl_down_sync(0xffffffffu, dq, o);
        }
        if (lane == 0) {
            g_psum[blockIdx.x]   = ds;
            g_psumsq[blockIdx.x] = dq;
            __threadfence();
            unsigned prev = atomicAdd(&g_count, 1u);
            isLast = (prev == RED_BLOCKS - 1);
        }
    }
    __syncthreads();

    if (isLast) {
        __threadfence();   // acquire all blocks' partials
        double ds = g_psum[t]       + g_psum[t + 128]
                  + g_psum[t + 256] + g_psum[t + 384];
        double dq = g_psumsq[t]       + g_psumsq[t + 128]
                  + g_psumsq[t + 256] + g_psumsq[t + 384];
        #pragma unroll
        for (int o = 16; o > 0; o >>= 1) {
            ds += __shfl_down_sync(0xffffffffu, ds, o);
            dq += __shfl_down_sync(0xffffffffu, dq, o);
        }
        __shared__ double fs[4], fq[4];
        if (lane == 0) { fs[warp] = ds; fq[warp] = dq; }
        __syncthreads();
        if (t == 0) {
            double S = (fs[0] + fs[1]) + (fs[2] + fs[3]);
            double Q = (fq[0] + fq[1]) + (fq[2] + fq[3]);
            double mean = S / (double)NELEM;
            double var  = Q / (double)NELEM - mean * mean;
            g_mean  = (float)mean;
            g_inv   = rsqrt_approx((float)var + 1e-5f);
            g_count = 0;   // reset for next graph replay
        }
    }
}

// ---------------------------------------------------------------------------
// K3: main — R15's proven lif VERBATIM (42.5us): two coalesced float4 delta
// loads from the transposed buffer, one thread = 8 l's as two disjoint
// 4-chunks (lA, lA+L/2), two independent 512B-burst float4 .cs stores per
// t, 1024 CTAs x 128 threads (balanced 6.92 CTAs/SM).
// out layout: [B, T, C, L] -> ((b*T + t)*C + c)*L + l
// ---------------------------------------------------------------------------
__global__ void __launch_bounds__(128) lif_kernel(
    const float* __restrict__ enc_w,
    const float* __restrict__ enc_b,
    const float* __restrict__ bn_gamma,
    const float* __restrict__ bn_beta,
    float* __restrict__ out)
{
    __shared__ float sw[T];
    __shared__ float sb[T];
    if (threadIdx.x < T) {
        sw[threadIdx.x] = enc_w[threadIdx.x];   // enc_w is [T,1]
        sb[threadIdx.x] = enc_b[threadIdx.x];
    }
    __syncthreads();

    const int idx = blockIdx.x * blockDim.x + threadIdx.x;  // 0 .. 131071
    const int lv  = idx & ((L / 8) - 1);        // 0..511
    const int c   = (idx >> 9) & (C - 1);
    const int b   = idx >> 12;
    const int lA  = lv * 4;                     // chunk A: [lA, lA+4)

    const float mean = g_mean;
    const float inv  = g_inv;
    const float ga   = bn_gamma[0];
    const float be   = bn_beta[0];

    // Coalesced transposed-delta loads (delta_t[b][c][l], 0 already at l==0)
    const float* drow = g_delta + ((long long)b * C + c) * L;
    float4 rA = *reinterpret_cast<const float4*>(drow + lA);
    float4 rB = *reinterpret_cast<const float4*>(drow + lA + (L / 2));

    float dA[4], dB[4];
    {
        const float* pa = &rA.x;
        const float* pb = &rB.x;
        #pragma unroll
        for (int j = 0; j < 4; ++j) {
            float xa = (pa[j] - mean) * inv;
            dA[j] = xa * ga + be;
            float xb = (pb[j] - mean) * inv;
            dB[j] = xb * ga + be;
        }
    }

    float vA0 = 0.f, vA1 = 0.f, vA2 = 0.f, vA3 = 0.f;
    float vB0 = 0.f, vB1 = 0.f, vB2 = 0.f, vB3 = 0.f;

    float* opA = out + (((long long)b * T) * C + c) * L + lA;
    float* opB = opA + (L / 2);

    #pragma unroll 8
    for (int t = 0; t < T; ++t) {
        const float w  = sw[t];
        const float bb = sb[t];
        const long long off = (long long)t * (C * L);
        float4 sa, sbv;

        float x;
        x = fmaf(dA[0], w, bb); vA0 = vA0 + (x - vA0) * 0.5f;
        bool p0 = (vA0 >= 1.0f); sa.x = p0 ? 1.0f : 0.0f; vA0 = p0 ? 0.0f : vA0;
        x = fmaf(dA[1], w, bb); vA1 = vA1 + (x - vA1) * 0.5f;
        bool p1 = (vA1 >= 1.0f); sa.y = p1 ? 1.0f : 0.0f; vA1 = p1 ? 0.0f : vA1;
        x = fmaf(dA[2], w, bb); vA2 = vA2 + (x - vA2) * 0.5f;
        bool p2 = (vA2 >= 1.0f); sa.z = p2 ? 1.0f : 0.0f; vA2 = p2 ? 0.0f : vA2;
        x = fmaf(dA[3], w, bb); vA3 = vA3 + (x - vA3) * 0.5f;
        bool p3 = (vA3 >= 1.0f); sa.w = p3 ? 1.0f : 0.0f; vA3 = p3 ? 0.0f : vA3;

        x = fmaf(dB[0], w, bb); vB0 = vB0 + (x - vB0) * 0.5f;
        bool q0 = (vB0 >= 1.0f); sbv.x = q0 ? 1.0f : 0.0f; vB0 = q0 ? 0.0f : vB0;
        x = fmaf(dB[1], w, bb); vB1 = vB1 + (x - vB1) * 0.5f;
        bool q1 = (vB1 >= 1.0f); sbv.y = q1 ? 1.0f : 0.0f; vB1 = q1 ? 0.0f : vB1;
        x = fmaf(dB[2], w, bb); vB2 = vB2 + (x - vB2) * 0.5f;
        bool q2 = (vB2 >= 1.0f); sbv.z = q2 ? 1.0f : 0.0f; vB2 = q2 ? 0.0f : vB2;
        x = fmaf(dB[3], w, bb); vB3 = vB3 + (x - vB3) * 0.5f;
        bool q3 = (vB3 >= 1.0f); sbv.w = q3 ? 1.0f : 0.0f; vB3 = q3 ? 0.0f : vB3;

        __stcs(reinterpret_cast<float4*>(opA + off), sa);
        __stcs(reinterpret_cast<float4*>(opB + off), sbv);
    }
}

// ---------------------------------------------------------------------------
extern "C" void kernel_launch(void* const* d_in, const int* in_sizes, int n_in,
                              void* d_out, int out_size)
{
    const float* in       = (const float*)d_in[0];
    const float* bn_gamma = (const float*)d_in[1];
    const float* bn_beta  = (const float*)d_in[2];
    const float* enc_w    = (const float*)d_in[3];
    const float* enc_b    = (const float*)d_in[4];
    float* out            = (float*)d_out;

    reduce_kernel<<<RED_BLOCKS, RED_THREADS>>>(in);

    const int total_thr = B * C * (L / 8);      // 131072
    lif_kernel<<<total_thr / 128, 128>>>(enc_w, enc_b, bn_gamma, bn_beta, out);
}